// round 12
// baseline (speedup 1.0000x reference)
#include <cuda_runtime.h>
#include <cuda_fp16.h>
#include <math.h>
#include <stdint.h>

#define NN 1024
#define HH 64

__device__ float  g_A[NN * HH];      // z_c @ W1[:64]
__device__ float  g_B[NN * HH];      // z_d @ W1[64:] + b1
__device__ float  g_expsum[NN];      // per-i sum_j exp(T1[i,j])
__device__ double g_acc;             // sum_i T1[i,i]  (diagonal == T0)

// ---------------------------------------------------------------------------
#define MMA16816(c, a0, a1, a2, a3, b0, b1)                                   \
    asm("mma.sync.aligned.m16n8k16.row.col.f32.f16.f16.f32 "                  \
        "{%0,%1,%2,%3}, {%4,%5,%6,%7}, {%8,%9}, {%0,%1,%2,%3};"               \
        : "+f"((c)[0]), "+f"((c)[1]), "+f"((c)[2]), "+f"((c)[3])              \
        : "r"(a0), "r"(a1), "r"(a2), "r"(a3), "r"(b0), "r"(b1))

__device__ __forceinline__ uint32_t pack_h2(float e0, float e1) {
    uint32_t r;
    asm("cvt.rn.f16x2.f32 %0, %1, %2;" : "=r"(r) : "f"(e1), "f"(e0));
    return r;
}

// ---------------------------------------------------------------------------
// Kernel 1: precompute A and B; zero the fused-softmax accumulators.
// ---------------------------------------------------------------------------
__global__ void prep_kernel(const float* __restrict__ zc,
                            const float* __restrict__ zd,
                            const float* __restrict__ W1,
                            const float* __restrict__ b1) {
    int which = blockIdx.y;
    if (blockIdx.x == 0 && which == 0) {
        for (int t = threadIdx.x; t < NN; t += 256) g_expsum[t] = 0.0f;
        if (threadIdx.x == 0) g_acc = 0.0;
    }
    int row = blockIdx.x * 4 + (threadIdx.x >> 6);
    int col = threadIdx.x & 63;
    const float* src = which ? zd : zc;
    const float* w   = W1 + (which ? 64 * HH : 0);
    float s0 = which ? b1[col] : 0.0f, s1 = 0.f, s2 = 0.f, s3 = 0.f;
#pragma unroll
    for (int k = 0; k < 64; k += 4) {
        s0 = fmaf(src[row * 64 + k],     w[(k) * HH + col],     s0);
        s1 = fmaf(src[row * 64 + k + 1], w[(k + 1) * HH + col], s1);
        s2 = fmaf(src[row * 64 + k + 2], w[(k + 2) * HH + col], s2);
        s3 = fmaf(src[row * 64 + k + 3], w[(k + 3) * HH + col], s3);
    }
    float s = (s0 + s1) + (s2 + s3);
    if (which) g_B[row * HH + col] = s;
    else       g_A[row * HH + col] = s;
}

// ---------------------------------------------------------------------------
// Kernel 2: pairwise MLP via HMMA (fp16 x fp16, fp32 acc), occ 3.
// R12: softmax fused into epilogue (exp + warp-reduce + atomicAdd per i);
//      accumulators initialized from b2 (drops 32 epilogue FADDs);
//      no T1 matrix, no lse kernel.
// ---------------------------------------------------------------------------
#define JSTRIDE 27   // CTAs per j-block; grid = 16 * 27 = 432 (1 wave at occ 3)

__global__ __launch_bounds__(128, 3) void pair_mma_kernel(
    const float* __restrict__ W2, const float* __restrict__ b2,
    const float* __restrict__ Wo, const float* __restrict__ bo_p) {
    __shared__ float sAT[64 * 68];   // [k][m], stride 68 (conflict-free frag reads)

    const int tid  = threadIdx.x;
    const int lane = tid & 31;
    const int wid  = tid >> 5;
    const int gid  = lane >> 2;      // 0..7
    const int tid4 = lane & 3;       // 0..3

    const int jb  = blockIdx.x / JSTRIDE;    // 0..15
    const int s0i = blockIdx.x % JSTRIDE;    // starting i
    const int j0  = jb * 64;

    // ---- stage A block transposed: sAT[k*68 + m] = g_A[(j0+m)*64 + k] ----
    for (int idx = tid; idx < 4096; idx += 128) {
        int m = idx >> 6, k = idx & 63;
        sAT[k * 68 + m] = g_A[(size_t)j0 * 64 + idx];
    }

    // ---- preload W2 fragments (fp16) into registers ----
    uint32_t Bf[4][8][2];
#pragma unroll
    for (int ks = 0; ks < 4; ++ks) {
#pragma unroll
        for (int nt = 0; nt < 8; ++nt) {
            int k0 = 16 * ks + 2 * tid4;
            int n  = 8 * nt + gid;
            Bf[ks][nt][0] = pack_h2(W2[(k0 + 0) * HH + n], W2[(k0 + 1) * HH + n]);
            Bf[ks][nt][1] = pack_h2(W2[(k0 + 8) * HH + n], W2[(k0 + 9) * HH + n]);
        }
    }

    // ---- per-thread epilogue constants ----
    float2 b2r[8], wor[8];
#pragma unroll
    for (int nt = 0; nt < 8; ++nt) {
        int n = 8 * nt + 2 * tid4;
        b2r[nt] = make_float2(b2[n], b2[n + 1]);
        wor[nt] = make_float2(Wo[n], Wo[n + 1]);
    }
    const float bo = bo_p[0];

    const int m0 = wid * 16 + gid;   // this thread's first row in j-block
    const int jA = j0 + m0;          // first j handled (epilogue rows)
    const int jB = j0 + m0 + 8;      // second j

    __syncthreads();                 // sAT ready (only barrier in kernel)

    // ---- prime the Bi pipeline for i = s0i ----
    float2 nbiL[4], nbiH[4];
    {
        const float* Bi = g_B + (size_t)s0i * 64;
#pragma unroll
        for (int ks = 0; ks < 4; ++ks) {
            const int k0 = 16 * ks + 2 * tid4;
            nbiL[ks] = *(const float2*)(Bi + k0);
            nbiH[ks] = *(const float2*)(Bi + k0 + 8);
        }
    }

    for (int i = s0i; i < NN; i += JSTRIDE) {
        float2 biL[4], biH[4];
#pragma unroll
        for (int ks = 0; ks < 4; ++ks) { biL[ks] = nbiL[ks]; biH[ks] = nbiH[ks]; }

        if (i + JSTRIDE < NN) {
            const float* Bn = g_B + (size_t)(i + JSTRIDE) * 64;
#pragma unroll
            for (int ks = 0; ks < 4; ++ks) {
                const int k0 = 16 * ks + 2 * tid4;
                nbiL[ks] = *(const float2*)(Bn + k0);
                nbiH[ks] = *(const float2*)(Bn + k0 + 8);
            }
        }

        // accumulators initialized from b2 (epilogue skips the +b2)
        float acc[8][4];
#pragma unroll
        for (int nt = 0; nt < 8; ++nt) {
            acc[nt][0] = b2r[nt].x;
            acc[nt][1] = b2r[nt].y;
            acc[nt][2] = b2r[nt].x;
            acc[nt][3] = b2r[nt].y;
        }

#pragma unroll
        for (int ks = 0; ks < 4; ++ks) {
            const int k0 = 16 * ks + 2 * tid4;

            const float* cL = sAT + k0 * 68 + m0;
            float h0 = fmaxf(cL[0]        + biL[ks].x, 0.f);
            float h1 = fmaxf(cL[68]       + biL[ks].y, 0.f);
            float h2 = fmaxf(cL[8 * 68]   + biH[ks].x, 0.f);
            float h3 = fmaxf(cL[9 * 68]   + biH[ks].y, 0.f);
            float h4 = fmaxf(cL[8]        + biL[ks].x, 0.f);
            float h5 = fmaxf(cL[68 + 8]   + biL[ks].y, 0.f);
            float h6 = fmaxf(cL[8*68 + 8] + biH[ks].x, 0.f);
            float h7 = fmaxf(cL[9*68 + 8] + biH[ks].y, 0.f);

            uint32_t a0 = pack_h2(h0, h1);
            uint32_t a1 = pack_h2(h4, h5);
            uint32_t a2 = pack_h2(h2, h3);
            uint32_t a3 = pack_h2(h6, h7);

#pragma unroll
            for (int nt = 0; nt < 8; ++nt)
                MMA16816(acc[nt], a0, a1, a2, a3,
                         Bf[ks][nt][0], Bf[ks][nt][1]);
        }

        // epilogue: T1 for rows jA (c0,c1) and jB (c2,c3)
        float sA0 = 0.f, sA1 = 0.f;
#pragma unroll
        for (int nt = 0; nt < 8; ++nt) {
            sA0 = fmaf(fmaxf(acc[nt][0], 0.f), wor[nt].x, sA0);
            sA0 = fmaf(fmaxf(acc[nt][1], 0.f), wor[nt].y, sA0);
            sA1 = fmaf(fmaxf(acc[nt][2], 0.f), wor[nt].x, sA1);
            sA1 = fmaf(fmaxf(acc[nt][3], 0.f), wor[nt].y, sA1);
        }
        sA0 += __shfl_xor_sync(0xffffffffu, sA0, 1);
        sA0 += __shfl_xor_sync(0xffffffffu, sA0, 2);
        sA1 += __shfl_xor_sync(0xffffffffu, sA1, 1);
        sA1 += __shfl_xor_sync(0xffffffffu, sA1, 2);

        const float t0 = sA0 + bo;      // T1[i, jA]  (valid on tid4 == 0)
        const float t1 = sA1 + bo;      // T1[i, jB]

        // fused softmax: warp-sum of exp(T1) over this warp's 16 j's
        float e = (tid4 == 0) ? (__expf(t0) + __expf(t1)) : 0.f;
#pragma unroll
        for (int o = 16; o > 0; o >>= 1)
            e += __shfl_xor_sync(0xffffffffu, e, o);
        if (lane == 0) atomicAdd(&g_expsum[i], e);

        // diagonal term (exactly one thread grid-wide per i)
        if (tid4 == 0) {
            if (jA == i) atomicAdd(&g_acc, (double)t0);
            if (jB == i) atomicAdd(&g_acc, (double)t1);
        }
    }
}

// ---------------------------------------------------------------------------
// Kernel 3: final reduction — sum_i log(expsum[i]), combine with diag sum.
// ---------------------------------------------------------------------------
__global__ void final_kernel(float* out) {
    __shared__ double red[32];
    const int tid = threadIdx.x;
    double v = log((double)g_expsum[tid]);
#pragma unroll
    for (int o = 16; o > 0; o >>= 1) v += __shfl_down_sync(0xffffffffu, v, o);
    if ((tid & 31) == 0) red[tid >> 5] = v;
    __syncthreads();
    if (tid < 32) {
        v = red[tid];
#pragma unroll
        for (int o = 16; o > 0; o >>= 1) v += __shfl_down_sync(0xffffffffu, v, o);
        if (tid == 0)
            out[0] = (float)(g_acc / NN - (v / NN - log((double)NN)));
    }
}

// ---------------------------------------------------------------------------
extern "C" void kernel_launch(void* const* d_in, const int* in_sizes, int n_in,
                              void* d_out, int out_size) {
    const float* z_c = (const float*)d_in[0];
    const float* z_d = (const float*)d_in[1];
    const float* W1  = (const float*)d_in[2];
    const float* b1  = (const float*)d_in[3];
    const float* W2  = (const float*)d_in[4];
    const float* b2  = (const float*)d_in[5];
    const float* Wo  = (const float*)d_in[6];
    const float* bo  = (const float*)d_in[7];
    float* out = (float*)d_out;

    prep_kernel<<<dim3(NN / 4, 2), 256>>>(z_c, z_d, W1, b1);
    pair_mma_kernel<<<16 * JSTRIDE, 128>>>(W2, b2, Wo, bo);
    final_kernel<<<1, 1024>>>(out);
}

// round 14
// speedup vs baseline: 1.0383x; 1.0383x over previous
#include <cuda_runtime.h>
#include <cuda_fp16.h>
#include <math.h>
#include <stdint.h>

#define NN 1024
#define HH 64

__device__ float    g_A[NN * HH];     // z_c @ W1[:64]  (fp32)
__device__ float    g_B[NN * HH];     // z_d @ W1[64:] + b1 (fp32)
__device__ uint32_t g_Bh[NN * 32];    // half2-packed B: [i][k2] = (B[2k2],B[2k2+1])
__device__ float    g_T1[NN * NN];
__device__ double   g_acc;
__device__ int      g_cnt;

// ---------------------------------------------------------------------------
#define MMA16816(c, a0, a1, a2, a3, b0, b1)                                   \
    asm("mma.sync.aligned.m16n8k16.row.col.f32.f16.f16.f32 "                  \
        "{%0,%1,%2,%3}, {%4,%5,%6,%7}, {%8,%9}, {%0,%1,%2,%3};"               \
        : "+f"((c)[0]), "+f"((c)[1]), "+f"((c)[2]), "+f"((c)[3])              \
        : "r"(a0), "r"(a1), "r"(a2), "r"(a3), "r"(b0), "r"(b1))

__device__ __forceinline__ uint32_t pack_h2(float e0, float e1) {  // lo=e0, hi=e1
    uint32_t r;
    asm("cvt.rn.f16x2.f32 %0, %1, %2;" : "=r"(r) : "f"(e1), "f"(e0));
    return r;
}
// relu(a + b) in packed fp16
__device__ __forceinline__ uint32_t frag_h2(uint32_t a, uint32_t b) {
    __half2 r = __hmax2(__hadd2(*(__half2*)&a, *(__half2*)&b),
                        __half2half2(__ushort_as_half(0)));
    return *(uint32_t*)&r;
}

// ---------------------------------------------------------------------------
// Kernel 1: precompute A (fp32) and B (fp32 + half2-packed copy).
// ---------------------------------------------------------------------------
__global__ void prep_kernel(const float* __restrict__ zc,
                            const float* __restrict__ zd,
                            const float* __restrict__ W1,
                            const float* __restrict__ b1) {
    int which = blockIdx.y;
    if (blockIdx.x == 0 && which == 0 && threadIdx.x == 0) {
        g_acc = 0.0;
        g_cnt = 0;
    }
    int row = blockIdx.x * 4 + (threadIdx.x >> 6);
    int col = threadIdx.x & 63;
    const float* src = which ? zd : zc;
    const float* w   = W1 + (which ? 64 * HH : 0);
    float s0 = which ? b1[col] : 0.0f, s1 = 0.f, s2 = 0.f, s3 = 0.f;
#pragma unroll
    for (int k = 0; k < 64; k += 4) {
        s0 = fmaf(src[row * 64 + k],     w[(k) * HH + col],     s0);
        s1 = fmaf(src[row * 64 + k + 1], w[(k + 1) * HH + col], s1);
        s2 = fmaf(src[row * 64 + k + 2], w[(k + 2) * HH + col], s2);
        s3 = fmaf(src[row * 64 + k + 3], w[(k + 3) * HH + col], s3);
    }
    float s = (s0 + s1) + (s2 + s3);
    if (which) {
        g_B[row * HH + col] = s;
        // cols are consecutive within a warp -> neighbor via shfl
        float s_hi = __shfl_down_sync(0xffffffffu, s, 1);
        if ((col & 1) == 0)
            g_Bh[row * 32 + (col >> 1)] = pack_h2(s, s_hi);
    } else {
        g_A[row * HH + col] = s;
    }
}

// ---------------------------------------------------------------------------
// Kernel 2: pairwise MLP via HMMA (fp16 x fp16, fp32 acc), occ 3.
// R13: fragment build fully in packed fp16 — A staged as half2 pairs in smem
//      (stride-72 words, conflict-free), B loaded as half2; per k-step the
//      A-fragments are 4 LDS + 4 HADD2 + 4 HMAX2, no CVT in the chain.
// ---------------------------------------------------------------------------
#define JSTRIDE 27   // CTAs per j-block; grid = 16 * 27 = 432 (1 wave at occ 3)

__global__ __launch_bounds__(128, 3) void pair_mma_kernel(
    const float* __restrict__ W2, const float* __restrict__ b2,
    const float* __restrict__ Wo, const float* __restrict__ bo_p) {
    __shared__ uint32_t sA2[32 * 72];   // [k2][m] half2(A[m][2k2],A[m][2k2+1])

    const int tid  = threadIdx.x;
    const int lane = tid & 31;
    const int wid  = tid >> 5;
    const int gid  = lane >> 2;      // 0..7
    const int tid4 = lane & 3;       // 0..3

    const int jb  = blockIdx.x / JSTRIDE;    // 0..15
    const int s0i = blockIdx.x % JSTRIDE;    // starting i
    const int j0  = jb * 64;

    // ---- stage A block as packed half2, transposed ----
    // idx: m = idx>>5 (0..63), k2 = idx&31  -> coalesced g_A float2 reads
    for (int idx = tid; idx < 2048; idx += 128) {
        int m = idx >> 5, k2 = idx & 31;
        float2 f = *(const float2*)(g_A + (size_t)(j0 + m) * 64 + 2 * k2);
        sA2[k2 * 72 + m] = pack_h2(f.x, f.y);
    }

    // ---- preload W2 fragments (fp16) into registers ----
    uint32_t Bf[4][8][2];
#pragma unroll
    for (int ks = 0; ks < 4; ++ks) {
#pragma unroll
        for (int nt = 0; nt < 8; ++nt) {
            int k0 = 16 * ks + 2 * tid4;
            int n  = 8 * nt + gid;
            Bf[ks][nt][0] = pack_h2(W2[(k0 + 0) * HH + n], W2[(k0 + 1) * HH + n]);
            Bf[ks][nt][1] = pack_h2(W2[(k0 + 8) * HH + n], W2[(k0 + 9) * HH + n]);
        }
    }

    // ---- per-thread epilogue constants ----
    float2 b2r[8], wor[8];
#pragma unroll
    for (int nt = 0; nt < 8; ++nt) {
        int n = 8 * nt + 2 * tid4;
        b2r[nt] = make_float2(b2[n], b2[n + 1]);
        wor[nt] = make_float2(Wo[n], Wo[n + 1]);
    }
    const float bo = bo_p[0];

    const int m0 = wid * 16 + gid;   // this thread's first row in j-block

    __syncthreads();                 // sA2 ready (only barrier in kernel)

    // ---- prime the Bi pipeline for i = s0i ----
    // bi[2ks+h] = g_Bh[i*32 + 8ks + 4h + tid4]
    uint32_t nbi[8];
    {
        const uint32_t* Bi = g_Bh + (size_t)s0i * 32;
#pragma unroll
        for (int ks = 0; ks < 4; ++ks) {
            nbi[2 * ks]     = Bi[8 * ks + tid4];
            nbi[2 * ks + 1] = Bi[8 * ks + 4 + tid4];
        }
    }

    for (int i = s0i; i < NN; i += JSTRIDE) {
        uint32_t bi[8];
#pragma unroll
        for (int q = 0; q < 8; ++q) bi[q] = nbi[q];

        if (i + JSTRIDE < NN) {
            const uint32_t* Bn = g_Bh + (size_t)(i + JSTRIDE) * 32;
#pragma unroll
            for (int ks = 0; ks < 4; ++ks) {
                nbi[2 * ks]     = Bn[8 * ks + tid4];
                nbi[2 * ks + 1] = Bn[8 * ks + 4 + tid4];
            }
        }

        // accumulators initialized from b2 (epilogue skips the +b2)
        float acc[8][4];
#pragma unroll
        for (int nt = 0; nt < 8; ++nt) {
            acc[nt][0] = b2r[nt].x;
            acc[nt][1] = b2r[nt].y;
            acc[nt][2] = b2r[nt].x;
            acc[nt][3] = b2r[nt].y;
        }

#pragma unroll
        for (int ks = 0; ks < 4; ++ks) {
            const int k2 = 8 * ks + tid4;
            // fragments: relu(A+B) in packed fp16, no CVT
            uint32_t a0 = frag_h2(sA2[k2 * 72 + m0],           bi[2 * ks]);
            uint32_t a1 = frag_h2(sA2[k2 * 72 + m0 + 8],       bi[2 * ks]);
            uint32_t a2 = frag_h2(sA2[(k2 + 4) * 72 + m0],     bi[2 * ks + 1]);
            uint32_t a3 = frag_h2(sA2[(k2 + 4) * 72 + m0 + 8], bi[2 * ks + 1]);

#pragma unroll
            for (int nt = 0; nt < 8; ++nt)
                MMA16816(acc[nt], a0, a1, a2, a3,
                         Bf[ks][nt][0], Bf[ks][nt][1]);
        }

        // epilogue: rows m0 (c0,c1) and m0+8 (c2,c3); acc already includes b2
        float sA0 = 0.f, sA1 = 0.f;
#pragma unroll
        for (int nt = 0; nt < 8; ++nt) {
            sA0 = fmaf(fmaxf(acc[nt][0], 0.f), wor[nt].x, sA0);
            sA0 = fmaf(fmaxf(acc[nt][1], 0.f), wor[nt].y, sA0);
            sA1 = fmaf(fmaxf(acc[nt][2], 0.f), wor[nt].x, sA1);
            sA1 = fmaf(fmaxf(acc[nt][3], 0.f), wor[nt].y, sA1);
        }
        sA0 += __shfl_xor_sync(0xffffffffu, sA0, 1);
        sA0 += __shfl_xor_sync(0xffffffffu, sA0, 2);
        sA1 += __shfl_xor_sync(0xffffffffu, sA1, 1);
        sA1 += __shfl_xor_sync(0xffffffffu, sA1, 2);
        if (tid4 == 0) {
            g_T1[(size_t)i * NN + j0 + m0]     = sA0 + bo;
            g_T1[(size_t)i * NN + j0 + m0 + 8] = sA1 + bo;
        }
    }
}

// ---------------------------------------------------------------------------
// Kernel 3: logsumexp + diagonal + fused final reduction (R11 form).
// ---------------------------------------------------------------------------
__global__ void lse_kernel(float* out) {
    __shared__ float sm[8], ss[8];
    const int tid = threadIdx.x;
    const int lane = tid & 31, wid = tid >> 5;
    double local = 0.0;

#pragma unroll 1
    for (int r = 0; r < 8; ++r) {
        const int i = blockIdx.x * 8 + r;
        const float4 v = ((const float4*)(g_T1 + (size_t)i * NN))[tid];

        float m = fmaxf(fmaxf(v.x, v.y), fmaxf(v.z, v.w));
#pragma unroll
        for (int o = 16; o > 0; o >>= 1)
            m = fmaxf(m, __shfl_xor_sync(0xffffffffu, m, o));
        if (lane == 0) sm[wid] = m;
        __syncthreads();
        float bm = sm[0];
#pragma unroll
        for (int w = 1; w < 8; ++w) bm = fmaxf(bm, sm[w]);

        float s = __expf(v.x - bm) + __expf(v.y - bm) +
                  __expf(v.z - bm) + __expf(v.w - bm);
#pragma unroll
        for (int o = 16; o > 0; o >>= 1)
            s += __shfl_xor_sync(0xffffffffu, s, o);
        if (lane == 0) ss[wid] = s;
        __syncthreads();

        if (tid == 0) {
            float tot = ss[0] + ss[1] + ss[2] + ss[3] +
                        ss[4] + ss[5] + ss[6] + ss[7];
            local += (double)g_T1[(size_t)i * NN + i]
                   - ((double)bm + log((double)tot));
        }
        __syncthreads();   // sm/ss safe to reuse next row
    }

    if (tid == 0) {
        atomicAdd(&g_acc, local);
        __threadfence();
        if (atomicAdd(&g_cnt, 1) == 127) {
            double acc = atomicAdd(&g_acc, 0.0);   // forced atomic read
            out[0] = (float)(acc / NN + log((double)NN));
        }
    }
}

// ---------------------------------------------------------------------------
extern "C" void kernel_launch(void* const* d_in, const int* in_sizes, int n_in,
                              void* d_out, int out_size) {
    const float* z_c = (const float*)d_in[0];
    const float* z_d = (const float*)d_in[1];
    const float* W1  = (const float*)d_in[2];
    const float* b1  = (const float*)d_in[3];
    const float* W2  = (const float*)d_in[4];
    const float* b2  = (const float*)d_in[5];
    const float* Wo  = (const float*)d_in[6];
    const float* bo  = (const float*)d_in[7];
    float* out = (float*)d_out;

    prep_kernel<<<dim3(NN / 4, 2), 256>>>(z_c, z_d, W1, b1);
    pair_mma_kernel<<<16 * JSTRIDE, 128>>>(W2, b2, Wo, bo);
    lse_kernel<<<128, 256>>>(out);
}